// round 14
// baseline (speedup 1.0000x reference)
#include <cuda_runtime.h>
#include <cuda_fp16.h>
#include <cstdint>

#define BB  4
#define CHN 128
#define HH  128
#define WW  128
#define HW  16384
#define K2C 1152
#define NPX (BB*HW)
#define NC  18                      // 64-k chunks

// ---------------- scratch (device globals; allocation-free) ----------------
__device__ __half g_xTh   [(size_t)NPX*CHN];   // x in NHWC, fp16
__device__ __half g_xattTh[(size_t)NPX*CHN];   // x_attned in NHWC, fp16
__device__ float g_attn [(size_t)BB*CHN*HW];   // sigmoid(conv_attn), NCHW
__device__ float g_feat [(size_t)BB*CHN*HW];   // raw conv_feat, NCHW
__device__ float g_xatt [(size_t)BB*CHN*HW];   // x_attned, NCHW
__device__ float g_off  [(size_t)BB*27*HW];    // 18 offsets + 9 sigmoided masks
__device__ float g_dconv[(size_t)BB*CHN*HW];   // deform conv output
// fp16 fragment-packed weights (m16n8k16 layout), indexed by 32-k chunks
__device__ __half g_wAh[36*2*4*4*32*8];        // [c32][ks2][hb4][mt4][lane][8] attn+feat
__device__ __half g_wth[36*2*2*4*32*8];        // [c32][ks2][hb2][mt4][lane][8] w_org
__device__ __half g_wMh[36*2*2*32*8];          // [c32][ks2][mt2][lane][8]      off/mask
__device__ float g_biasA[256];
__device__ float g_biasM[32];
__device__ float g_biasO[128];
__device__ float g_stats[2*BB*CHN*2];

__device__ __forceinline__ float sigmoidf(float v) { return 1.0f/(1.0f + __expf(-v)); }

__device__ __forceinline__ void mma_f16(float* d, const uint32_t* a,
                                        uint32_t b0, uint32_t b1) {
    asm volatile(
        "mma.sync.aligned.m16n8k16.row.col.f32.f16.f16.f32 "
        "{%0,%1,%2,%3},{%4,%5,%6,%7},{%8,%9},{%0,%1,%2,%3};\n"
        : "+f"(d[0]), "+f"(d[1]), "+f"(d[2]), "+f"(d[3])
        : "r"(a[0]), "r"(a[1]), "r"(a[2]), "r"(a[3]), "r"(b0), "r"(b1));
}

__device__ __forceinline__ void cp16(unsigned dst, const void* src, int srcsize) {
    asm volatile("cp.async.cg.shared.global [%0], [%1], 16, %2;\n"
                 :: "r"(dst), "l"(src), "r"(srcsize));
}
__device__ __forceinline__ void cp_commit() { asm volatile("cp.async.commit_group;\n"); }
__device__ __forceinline__ void cp_wait0()  { asm volatile("cp.async.wait_group 0;\n"); }
__device__ __forceinline__ void cp_wait1()  { asm volatile("cp.async.wait_group 1;\n"); }

// ---------------- prep: pack weights into fp16 fragments ----------------
__global__ void prep_k(const float* __restrict__ w_attn, const float* __restrict__ w_feat,
                       const float* __restrict__ w_org,  const float* __restrict__ w_off,
                       const float* __restrict__ w_mask,
                       const float* __restrict__ b_attn, const float* __restrict__ b_feat,
                       const float* __restrict__ b_org,  const float* __restrict__ b_off,
                       const float* __restrict__ b_mask)
{
    int i = blockIdx.x*256 + threadIdx.x;       // 0 .. 294911
    {   // g_wAh
        int e = i & 7, lane = (i>>3) & 31, mt = (i>>8) & 3,
            hb = (i>>10) & 3, ks = (i>>12) & 1, c = i >> 13;
        int g = lane>>2, tig = lane&3, r = e>>1, h = e&1;
        int co = hb*64 + mt*16 + g + ((r&1) ? 8 : 0);
        int k  = c*32 + ks*16 + tig*2 + h + ((r&2) ? 8 : 0);
        int tap = k >> 7, ci = k & 127;
        float v = (co < 128) ? w_attn[(co*128+ci)*9 + tap]
                             : w_feat[((co-128)*128+ci)*9 + tap];
        g_wAh[i] = __float2half(v);
    }
    if (i < 36*2*2*4*32*8) {   // g_wth
        int e = i & 7, lane = (i>>3) & 31, mt = (i>>8) & 3,
            hb = (i>>10) & 1, ks = (i>>11) & 1, c = i >> 12;
        int g = lane>>2, tig = lane&3, r = e>>1, h = e&1;
        int co = hb*64 + mt*16 + g + ((r&1) ? 8 : 0);
        int k  = c*32 + ks*16 + tig*2 + h + ((r&2) ? 8 : 0);
        int tap = k >> 7, ci = k & 127;
        g_wth[i] = __float2half(w_org[(co*128+ci)*9 + tap]);
    }
    if (i < 36*2*2*32*8) {     // g_wMh
        int e = i & 7, lane = (i>>3) & 31, mt = (i>>8) & 1,
            ks = (i>>9) & 1, c = i >> 10;
        int g = lane>>2, tig = lane&3, r = e>>1, h = e&1;
        int co = mt*16 + g + ((r&1) ? 8 : 0);
        int k  = c*32 + ks*16 + tig*2 + h + ((r&2) ? 8 : 0);
        int tap = k >> 7, ci = k & 127;
        float v = 0.f;
        if (co < 18)      v = w_off [(co*128+ci)*9 + tap];
        else if (co < 27) v = w_mask[((co-18)*128+ci)*9 + tap];
        g_wMh[i] = __float2half(v);
    }
    if (i < 256) g_biasA[i] = (i < 128) ? b_attn[i] : b_feat[i-128];
    if (i < 128) g_biasO[i] = b_org[i];
    if (i < 32)  g_biasM[i] = (i < 18) ? b_off[i] : (i < 27 ? b_mask[i-18] : 0.f);
    if (i < 2*BB*CHN*2) g_stats[i] = 0.f;
}

// ---------------- NCHW -> NHWC(fp16) transpose of x ----------------
__global__ __launch_bounds__(256) void transpose_k(const float* __restrict__ x) {
    __shared__ float s[32][133];
    int bid = blockIdx.x;
    int pg = bid & 127, cg = (bid >> 7) & 3, b = bid >> 9;
    int t = threadIdx.x;
    int px0 = pg << 7;
    #pragma unroll
    for (int j = 0; j < 16; j++) {
        int idx = t + j*256;
        int ch = idx >> 7, px = idx & 127;
        s[ch][px] = x[((size_t)(b*CHN + (cg<<5) + ch) << 14) + px0 + px];
    }
    __syncthreads();
    #pragma unroll
    for (int j = 0; j < 16; j++) {
        int idx = t + j*256;
        int px = idx >> 5, ch = idx & 31;
        g_xTh[((size_t)((b<<14) + px0 + px))*CHN + (cg<<5) + ch] = __float2half(s[ch][px]);
    }
}

// ---------------- generic fp16 GEMM, 64-k chunks -------------------------
// MODE 0: attn+feat conv; MODE 1: off/mask conv;
// MODE 2: fused deform einsum with smem-windowed gather
template<int MODE>
__global__ __launch_bounds__(256, 2) void gemm_k()
{
    constexpr int MT     = (MODE==1) ? 2 : 4;
    constexpr int NT     = (MODE==1) ? 2 : 4;
    constexpr int NH     = (MODE==1) ? 1 : 2;
    constexpr int A_H    = (MODE==1) ? 2048 : 8192;   // halves per stage
    constexpr int B_H    = 128*72;                    // 9216 halves per stage
    constexpr int STAGES = (MODE==2) ? 2 : 3;
    constexpr int WIN_H  = 4*128*128;                 // MODE2 row window (halves)
    extern __shared__ __half smh[];
    __half* smwin = smh;                                        // MODE2 only
    __half* as  = (MODE==2) ? (smh + WIN_H) : smh;
    __half* bsm = as + STAGES*A_H;
    __half* cwH = bsm + STAGES*B_H;                             // MODE2: 4608 halves
    short*  ciS = (short*)(cwH + 4608);                         // MODE2: 4608 shorts

    const int t = threadIdx.x;
    const int wid = t >> 5, lane = t & 31, g = lane >> 2, tig = lane & 3;
    const int px0 = blockIdx.x << 7;
    const int bI = px0 >> 14, y = (px0 >> 7) & 127;
    const int yblk = (MODE==0) ? blockIdx.y : 0;
    const int co0 = yblk << 7;
    const int halfsel = (MODE==1) ? 0 : (wid >> 2);
    const int cow = halfsel * 64;
    const int pxw = (MODE==1) ? (wid << 4) : ((wid & 3) << 5);

    float acc[MT][NT][4];
    #pragma unroll
    for (int mt = 0; mt < MT; mt++)
        #pragma unroll
        for (int nt = 0; nt < NT; nt++)
            #pragma unroll
            for (int j = 0; j < 4; j++) acc[mt][nt][j] = 0.f;

    // ---- MODE2: window row loader (32KB via cp.async; caller commits) ----
    auto load_wrow = [&](int imgrow, int slot) {
        int rc = min(max(imgrow, 0), HH-1);
        const __half* src = g_xattTh + ((size_t)((bI<<14) + (rc<<7)))*CHN;
        #pragma unroll
        for (int j = 0; j < 8; j++) {
            int idx = t + j*256;            // 2048 cp16s
            unsigned d = (unsigned)__cvta_generic_to_shared(
                smwin + slot*16384 + idx*8);
            cp16(d, src + idx*8, 16);
        }
    };

    // ---- staging helper (caller commits); c = 64-k chunk index ----
    auto stage = [&](int c, int buf) {
        if (MODE == 0) {
            #pragma unroll
            for (int j = 0; j < 4; j++) {
                int idx = t + j*256;                 // 1024 cp16s
                int sub = idx >> 9, oks = (idx >> 8) & 1, off = idx & 255;
                unsigned d = (unsigned)__cvta_generic_to_shared(as + buf*A_H + idx*8);
                cp16(d, g_wAh + (size_t)(2*c+sub)*8192 + oks*4096 + yblk*2048 + off*8, 16);
            }
        } else if (MODE == 2) {
            #pragma unroll
            for (int j = 0; j < 4; j++) {
                int idx = t + j*256;
                int sub = idx >> 9, rest = idx & 511;
                unsigned d = (unsigned)__cvta_generic_to_shared(as + buf*A_H + idx*8);
                cp16(d, g_wth + (size_t)(2*c+sub)*4096 + rest*8, 16);
            }
            if (c == 5) load_wrow(y+1, 3);
            if (c == 6) load_wrow(y+2, 0);
        } else {
            int sub = t >> 7, rest = t & 127;
            unsigned d = (unsigned)__cvta_generic_to_shared(as + buf*A_H + t*8);
            cp16(d, g_wMh + (size_t)(2*c+sub)*1024 + rest*8, 16);
        }
        if (MODE != 2) {
            const __half* srcT = (MODE==0) ? g_xTh : g_xattTh;
            int tap = c >> 1, ci0 = (c & 1) << 6;
            int dy = tap/3 - 1, dxx = tap - (tap/3)*3 - 1;
            int row = t >> 1;
            int yp = y + dy, xp = row + dxx;
            bool valid = ((unsigned)yp < 128u) && ((unsigned)xp < 128u);
            int sz = valid ? 16 : 0;
            const __half* src = srcT + ((size_t)((bI<<14) + (valid ? (yp<<7)+xp : 0)))*CHN + ci0;
            #pragma unroll
            for (int j = 0; j < 4; j++) {
                int seg = (t & 1)*4 + j;             // 0..7, 16B each
                unsigned d = (unsigned)__cvta_generic_to_shared(
                    bsm + buf*B_H + row*72 + seg*8);
                cp16(d, src + seg*8, sz);
            }
        }
    };

    // ==================== MODE 0 / 1: 3-stage pipeline ====================
    if (MODE != 2) {
        stage(0, 0); cp_commit();
        stage(1, 1); cp_commit();
        for (int c = 0; c < NC; c++) {
            if (c < NC-1) cp_wait1(); else cp_wait0();
            __syncthreads();
            if (c + 2 < NC) { stage(c+2, (c+2)%3); cp_commit(); }
            const uint4*  ab = (const uint4*)(as + (c%3)*A_H);
            const __half* bb = bsm + (c%3)*B_H;
            #pragma unroll
            for (int s = 0; s < 4; s++) {
                uint4 af[MT];
                #pragma unroll
                for (int mt = 0; mt < MT; mt++)
                    af[mt] = ab[(s*NH + halfsel)*MT*32 + mt*32 + lane];
                #pragma unroll
                for (int nt = 0; nt < NT; nt++) {
                    const __half* bp = bb + (pxw + nt*8 + g)*72 + s*16 + tig*2;
                    uint32_t b0 = *(const uint32_t*)bp;
                    uint32_t b1 = *(const uint32_t*)(bp + 8);
                    #pragma unroll
                    for (int mt = 0; mt < MT; mt++)
                        mma_f16(acc[mt][nt], (const uint32_t*)&af[mt], b0, b1);
                }
            }
        }
    }
    // ====== MODE 2: window gather + 2-stage pipeline ======================
    else {
        // prologue: issue window rows y-2..y (slots 0,1,2) + A chunk 0
        load_wrow(y-2, 0);
        load_wrow(y-1, 1);
        load_wrow(y,   2);
        stage(0, 0); cp_commit();

        // corner tables: fp16 weights + int16 window index (slot*128+xc)
        {
            const float* ob = g_off + (((size_t)bI*27) << 14) + y*WW;
            for (int pt = t; pt < 1152; pt += 256) {
                int tap = pt >> 7, px = pt & 127;
                float dy = ob[((size_t)(2*tap  ) << 14) + px];
                float dx = ob[((size_t)(2*tap+1) << 14) + px];
                float mk = ob[((size_t)(18+tap ) << 14) + px];
                float yy = dy + (float)(y  + tap/3 - 1);
                float xx = dx + (float)(px + tap%3 - 1);
                float y0f = floorf(yy), x0f = floorf(xx);
                float wy = yy - y0f, wx = xx - x0f;
                int y0 = (int)y0f, x0 = (int)x0f;
                float fw[4]; short fi[4];
                #pragma unroll
                for (int cnr = 0; cnr < 4; cnr++) {
                    int ddy = cnr >> 1, ddx = cnr & 1;
                    int yi = y0 + ddy, xi = x0 + ddx;
                    bool valid = ((unsigned)yi < (unsigned)HH) && ((unsigned)xi < (unsigned)WW);
                    int yc = min(max(yi, 0), HH-1);
                    int xc = min(max(xi, 0), WW-1);
                    float wgt = (ddy ? wy : 1.f - wy) * (ddx ? wx : 1.f - wx) * mk;
                    fw[cnr] = valid ? wgt : 0.f;
                    fi[cnr] = (short)((((yc - y + 2) & 3) << 7) + xc);
                }
                ((__half2*)cwH)[pt*2]   = __floats2half2_rn(fw[0], fw[1]);
                ((__half2*)cwH)[pt*2+1] = __floats2half2_rn(fw[2], fw[3]);
                ((short4*)ciS)[pt] = make_short4(fi[0], fi[1], fi[2], fi[3]);
            }
        }
        cp_wait0(); __syncthreads();     // window rows 0-2 + A0 ready, tables visible

        // gather chunk 0 (tap 0, ci 0..63) from window
        #pragma unroll
        for (int hh = 0; hh < 2; hh++) {
            int ci = hh*32 + lane;
            __half* bd = bsm + hh*32 + lane;
            #pragma unroll 4
            for (int idx = 0; idx < 16; idx++) {
                int px = wid + idx*8;
                float2 f01 = __half22float2(((const __half2*)cwH)[px*2]);
                float2 f23 = __half22float2(((const __half2*)cwH)[px*2+1]);
                short4 s4  = ((const short4*)ciS)[px];
                float v = f01.x*__half2float(smwin[(int)s4.x*128 + ci])
                        + f01.y*__half2float(smwin[(int)s4.y*128 + ci])
                        + f23.x*__half2float(smwin[(int)s4.z*128 + ci])
                        + f23.y*__half2float(smwin[(int)s4.w*128 + ci]);
                bd[px*72] = __float2half(v);
            }
        }
        __syncthreads();

        for (int c = 0; c < NC; c++) {
            const int buf = c & 1;
            if (c < NC-1) { stage(c+1, buf^1); cp_commit(); }

            int tapn = 0, cib_n = 0; __half* bdb = nullptr;
            if (c < NC-1) {
                int cn = c + 1;
                tapn = cn >> 1; cib_n = (cn & 1) << 6;
                bdb = bsm + (buf^1)*B_H;
            }

            const uint4*  ab = (const uint4*)(as + buf*A_H);
            const __half* bb = bsm + buf*B_H;
            #pragma unroll
            for (int s = 0; s < 4; s++) {
                uint4 af[MT];
                #pragma unroll
                for (int mt = 0; mt < MT; mt++)
                    af[mt] = ab[(s*2 + halfsel)*128 + mt*32 + lane];
                #pragma unroll
                for (int sub = 0; sub < 2; sub++) {
                    const int sl = s*2 + sub;            // 0..7
                    const int hh = sl >> 2, qb = sl & 3;
                    #pragma unroll
                    for (int nt = sub*2; nt < sub*2 + 2; nt++) {
                        const __half* bp = bb + (pxw + nt*8 + g)*72 + s*16 + tig*2;
                        uint32_t b0 = *(const uint32_t*)bp;
                        uint32_t b1 = *(const uint32_t*)(bp + 8);
                        #pragma unroll
                        for (int mt = 0; mt < MT; mt++)
                            mma_f16(acc[mt][nt], (const uint32_t*)&af[mt], b0, b1);
                    }
                    if (c < NC-1) {
                        int ci = cib_n + hh*32 + lane;
                        __half* bd = bdb + hh*32 + lane;
                        #pragma unroll
                        for (int q = 0; q < 4; q++) {
                            int px = wid + (qb*4 + q)*8;
                            int pt = tapn*128 + px;
                            float2 f01 = __half22float2(((const __half2*)cwH)[pt*2]);
                            float2 f23 = __half22float2(((const __half2*)cwH)[pt*2+1]);
                            short4 s4  = ((const short4*)ciS)[pt];
                            float v = f01.x*__half2float(smwin[(int)s4.x*128 + ci])
                                    + f01.y*__half2float(smwin[(int)s4.y*128 + ci])
                                    + f23.x*__half2float(smwin[(int)s4.z*128 + ci])
                                    + f23.y*__half2float(smwin[(int)s4.w*128 + ci]);
                            bd[px*72] = __float2half(v);
                        }
                    }
                }
            }
            if (c < NC-1) { cp_wait0(); __syncthreads(); }
        }
    }

    // ---- epilogue ----
    const int prem = px0 & (HW-1);
    #pragma unroll
    for (int mt = 0; mt < MT; mt++) {
        #pragma unroll
        for (int r = 0; r < 2; r++) {
            const int coL = cow + mt*16 + r*8 + g;
            const int coG = co0 + coL;
            float bv = 0.f; float* plane = nullptr;
            bool sig = false, dostats = false; int sidx = 0;
            if (MODE == 0) {
                bv = g_biasA[coG];
                if (coG < 128) { plane = g_attn + ((size_t)(bI*CHN + coG) << 14); sig = true; }
                else {
                    plane = g_feat + ((size_t)(bI*CHN + coG - 128) << 14);
                    dostats = true; sidx = (bI*CHN + coG - 128)*2;
                }
            } else if (MODE == 2) {
                bv = g_biasO[coL];
                plane = g_dconv + ((size_t)(bI*CHN + coL) << 14);
                dostats = true; sidx = (BB*CHN + bI*CHN + coL)*2;
            } else {
                bv = g_biasM[coL];
                if (coL < 27) { plane = g_off + ((size_t)(bI*27 + coL) << 14); sig = (coL >= 18); }
            }
            float s = 0.f, q = 0.f;
            #pragma unroll
            for (int nt = 0; nt < NT; nt++) {
                float v0 = acc[mt][nt][r*2]   + bv;
                float v1 = acc[mt][nt][r*2+1] + bv;
                if (sig) { v0 = sigmoidf(v0); v1 = sigmoidf(v1); }
                int col = pxw + nt*8 + 2*tig;
                if (plane) *(float2*)&plane[prem + col] = make_float2(v0, v1);
                s += v0 + v1; q += v0*v0 + v1*v1;
            }
            if (dostats) {
                s += __shfl_xor_sync(0xffffffffu, s, 1);
                s += __shfl_xor_sync(0xffffffffu, s, 2);
                q += __shfl_xor_sync(0xffffffffu, q, 1);
                q += __shfl_xor_sync(0xffffffffu, q, 2);
                if (tig == 0) {
                    atomicAdd(&g_stats[sidx],   s);
                    atomicAdd(&g_stats[sidx+1], q);
                }
            }
        }
    }
}

// ---- x_attned = lrelu(IN(feat)) * attn ; NCHW fp32 + NHWC fp16 ----
__global__ __launch_bounds__(256) void xatt_k() {
    __shared__ float s[32][133];
    int bid = blockIdx.x;
    int pg = bid & 127, cg = (bid >> 7) & 3, b = bid >> 9;
    int t = threadIdx.x;
    int px0 = pg << 7;
    #pragma unroll
    for (int j = 0; j < 16; j++) {
        int idx = t + j*256;
        int ch = idx >> 7, px = idx & 127;
        int plane = b*CHN + (cg<<5) + ch;
        size_t gi = ((size_t)plane << 14) + px0 + px;
        float su = g_stats[2*plane], sq = g_stats[2*plane+1];
        float mu = su * (1.0f/HW);
        float rs = rsqrtf(sq * (1.0f/HW) - mu*mu + 1e-5f);
        float v = (g_feat[gi] - mu)*rs;
        v = v > 0.f ? v : 0.2f*v;
        float o = v * g_attn[gi];
        g_xatt[gi] = o;
        s[ch][px] = o;
    }
    __syncthreads();
    #pragma unroll
    for (int j = 0; j < 16; j++) {
        int idx = t + j*256;
        int px = idx >> 5, ch = idx & 31;
        g_xattTh[((size_t)((b<<14) + px0 + px))*CHN + (cg<<5) + ch] =
            __float2half(s[ch][px]);
    }
}

// ---- final: out = xatt + lrelu(IN(dconv)) * (1 - attn) ----
__global__ void final_k(float* __restrict__ out) {
    int i = blockIdx.x*256 + threadIdx.x;
    int plane = i >> 12;
    float su = g_stats[2*(BB*CHN + plane)], sq = g_stats[2*(BB*CHN + plane)+1];
    float mu = su * (1.0f/HW);
    float rs = rsqrtf(sq * (1.0f/HW) - mu*mu + 1e-5f);
    float4 d  = ((const float4*)g_dconv)[i];
    float4 a  = ((const float4*)g_attn)[i];
    float4 xa = ((const float4*)g_xatt)[i];
    float4 o; float v;
    v = (d.x - mu)*rs; v = v > 0.f ? v : 0.2f*v; o.x = xa.x + v*(1.f - a.x);
    v = (d.y - mu)*rs; v = v > 0.f ? v : 0.2f*v; o.y = xa.y + v*(1.f - a.y);
    v = (d.z - mu)*rs; v = v > 0.f ? v : 0.2f*v; o.z = xa.z + v*(1.f - a.z);
    v = (d.w - mu)*rs; v = v > 0.f ? v : 0.2f*v; o.w = xa.w + v*(1.f - a.w);
    ((float4*)out)[i] = o;
}

// ---------------- launch ----------------
extern "C" void kernel_launch(void* const* d_in, const int* in_sizes, int n_in,
                              void* d_out, int out_size) {
    const float* x      = (const float*)d_in[0];
    const float* w_attn = (const float*)d_in[1];
    const float* b_attn = (const float*)d_in[2];
    const float* w_feat = (const float*)d_in[3];
    const float* b_feat = (const float*)d_in[4];
    const float* w_org  = (const float*)d_in[5];
    const float* b_org  = (const float*)d_in[6];
    const float* w_off  = (const float*)d_in[7];
    const float* b_off  = (const float*)d_in[8];
    const float* w_mask = (const float*)d_in[9];
    const float* b_mask = (const float*)d_in[10];
    float* out = (float*)d_out;

    const int SM_M0 = 3*(8192 + 9216)*2;                     // 104448
    const int SM_M1 = 3*(2048 + 9216)*2;                     // 67584
    const int SM_M2 = (4*128*128)*2 + 2*(8192+9216)*2
                      + 4608*2 + 4608*2;                     // 219136
    cudaFuncSetAttribute(gemm_k<0>, cudaFuncAttributeMaxDynamicSharedMemorySize, SM_M0);
    cudaFuncSetAttribute(gemm_k<1>, cudaFuncAttributeMaxDynamicSharedMemorySize, SM_M1);
    cudaFuncSetAttribute(gemm_k<2>, cudaFuncAttributeMaxDynamicSharedMemorySize, SM_M2);

    prep_k<<<1152, 256>>>(w_attn, w_feat, w_org, w_off, w_mask,
                          b_attn, b_feat, b_org, b_off, b_mask);
    transpose_k<<<2048, 256>>>(x);
    gemm_k<0><<<dim3(512, 2), 256, SM_M0>>>();     // attn + feat conv
    xatt_k<<<2048, 256>>>();
    gemm_k<1><<<512, 256, SM_M1>>>();              // offset + mask conv
    gemm_k<2><<<512, 256, SM_M2>>>();              // windowed deform einsum
    final_k<<<8192, 256>>>(out);
}

// round 15
// speedup vs baseline: 1.0492x; 1.0492x over previous
#include <cuda_runtime.h>
#include <cuda_fp16.h>
#include <cstdint>

#define BB  4
#define CHN 128
#define HH  128
#define WW  128
#define HW  16384
#define K2C 1152
#define NPX (BB*HW)
#define NC  18                      // 64-k chunks

// ---------------- scratch (device globals; allocation-free) ----------------
__device__ __half g_xTh   [(size_t)NPX*CHN];   // x in NHWC, fp16
__device__ __half g_xattTh[(size_t)NPX*CHN];   // x_attned in NHWC, fp16
__device__ __half g_attnH [(size_t)BB*CHN*HW]; // sigmoid(conv_attn), NCHW fp16
__device__ __half g_featH [(size_t)BB*CHN*HW]; // raw conv_feat, NCHW fp16
__device__ float g_off  [(size_t)BB*27*HW];    // 18 offsets + 9 sigmoided masks
__device__ float g_dconv[(size_t)BB*CHN*HW];   // deform conv output, fp32
// fp16 fragment-packed weights (m16n8k16 layout), indexed by 32-k chunks
__device__ __half g_wAh[36*2*4*4*32*8];        // [c32][ks2][hb4][mt4][lane][8] attn+feat
__device__ __half g_wth[36*2*2*4*32*8];        // [c32][ks2][hb2][mt4][lane][8] w_org
__device__ __half g_wMh[36*2*2*32*8];          // [c32][ks2][mt2][lane][8]      off/mask
__device__ float g_biasA[256];
__device__ float g_biasM[32];
__device__ float g_biasO[128];
__device__ float g_stats[2*BB*CHN*2];

__device__ __forceinline__ float sigmoidf(float v) { return 1.0f/(1.0f + __expf(-v)); }

__device__ __forceinline__ void mma_f16(float* d, const uint32_t* a,
                                        uint32_t b0, uint32_t b1) {
    asm volatile(
        "mma.sync.aligned.m16n8k16.row.col.f32.f16.f16.f32 "
        "{%0,%1,%2,%3},{%4,%5,%6,%7},{%8,%9},{%0,%1,%2,%3};\n"
        : "+f"(d[0]), "+f"(d[1]), "+f"(d[2]), "+f"(d[3])
        : "r"(a[0]), "r"(a[1]), "r"(a[2]), "r"(a[3]), "r"(b0), "r"(b1));
}

__device__ __forceinline__ void cp16(unsigned dst, const void* src, int srcsize) {
    asm volatile("cp.async.cg.shared.global [%0], [%1], 16, %2;\n"
                 :: "r"(dst), "l"(src), "r"(srcsize));
}
__device__ __forceinline__ void cp_commit() { asm volatile("cp.async.commit_group;\n"); }
__device__ __forceinline__ void cp_wait0()  { asm volatile("cp.async.wait_group 0;\n"); }
__device__ __forceinline__ void cp_wait1()  { asm volatile("cp.async.wait_group 1;\n"); }

// ---------------- prep: pack weights into fp16 fragments ----------------
__global__ void prep_k(const float* __restrict__ w_attn, const float* __restrict__ w_feat,
                       const float* __restrict__ w_org,  const float* __restrict__ w_off,
                       const float* __restrict__ w_mask,
                       const float* __restrict__ b_attn, const float* __restrict__ b_feat,
                       const float* __restrict__ b_org,  const float* __restrict__ b_off,
                       const float* __restrict__ b_mask)
{
    int i = blockIdx.x*256 + threadIdx.x;       // 0 .. 294911
    {   // g_wAh
        int e = i & 7, lane = (i>>3) & 31, mt = (i>>8) & 3,
            hb = (i>>10) & 3, ks = (i>>12) & 1, c = i >> 13;
        int g = lane>>2, tig = lane&3, r = e>>1, h = e&1;
        int co = hb*64 + mt*16 + g + ((r&1) ? 8 : 0);
        int k  = c*32 + ks*16 + tig*2 + h + ((r&2) ? 8 : 0);
        int tap = k >> 7, ci = k & 127;
        float v = (co < 128) ? w_attn[(co*128+ci)*9 + tap]
                             : w_feat[((co-128)*128+ci)*9 + tap];
        g_wAh[i] = __float2half(v);
    }
    if (i < 36*2*2*4*32*8) {   // g_wth
        int e = i & 7, lane = (i>>3) & 31, mt = (i>>8) & 3,
            hb = (i>>10) & 1, ks = (i>>11) & 1, c = i >> 12;
        int g = lane>>2, tig = lane&3, r = e>>1, h = e&1;
        int co = hb*64 + mt*16 + g + ((r&1) ? 8 : 0);
        int k  = c*32 + ks*16 + tig*2 + h + ((r&2) ? 8 : 0);
        int tap = k >> 7, ci = k & 127;
        g_wth[i] = __float2half(w_org[(co*128+ci)*9 + tap]);
    }
    if (i < 36*2*2*32*8) {     // g_wMh
        int e = i & 7, lane = (i>>3) & 31, mt = (i>>8) & 1,
            ks = (i>>9) & 1, c = i >> 10;
        int g = lane>>2, tig = lane&3, r = e>>1, h = e&1;
        int co = mt*16 + g + ((r&1) ? 8 : 0);
        int k  = c*32 + ks*16 + tig*2 + h + ((r&2) ? 8 : 0);
        int tap = k >> 7, ci = k & 127;
        float v = 0.f;
        if (co < 18)      v = w_off [(co*128+ci)*9 + tap];
        else if (co < 27) v = w_mask[((co-18)*128+ci)*9 + tap];
        g_wMh[i] = __float2half(v);
    }
    if (i < 256) g_biasA[i] = (i < 128) ? b_attn[i] : b_feat[i-128];
    if (i < 128) g_biasO[i] = b_org[i];
    if (i < 32)  g_biasM[i] = (i < 18) ? b_off[i] : (i < 27 ? b_mask[i-18] : 0.f);
    if (i < 2*BB*CHN*2) g_stats[i] = 0.f;
}

// ---------------- NCHW -> NHWC(fp16) transpose of x ----------------
__global__ __launch_bounds__(256) void transpose_k(const float* __restrict__ x) {
    __shared__ float s[32][133];
    int bid = blockIdx.x;
    int pg = bid & 127, cg = (bid >> 7) & 3, b = bid >> 9;
    int t = threadIdx.x;
    int px0 = pg << 7;
    #pragma unroll
    for (int j = 0; j < 16; j++) {
        int idx = t + j*256;
        int ch = idx >> 7, px = idx & 127;
        s[ch][px] = x[((size_t)(b*CHN + (cg<<5) + ch) << 14) + px0 + px];
    }
    __syncthreads();
    #pragma unroll
    for (int j = 0; j < 16; j++) {
        int idx = t + j*256;
        int px = idx >> 5, ch = idx & 31;
        g_xTh[((size_t)((b<<14) + px0 + px))*CHN + (cg<<5) + ch] = __float2half(s[ch][px]);
    }
}

// ---------------- generic fp16 GEMM, 64-k chunks -------------------------
// MODE 0: attn+feat conv; MODE 1: off/mask conv; MODE 2: fused deform einsum
template<int MODE>
__global__ __launch_bounds__(256, 2) void gemm_k()
{
    constexpr int MT     = (MODE==1) ? 2 : 4;
    constexpr int NT     = (MODE==1) ? 2 : 4;
    constexpr int NH     = (MODE==1) ? 1 : 2;
    constexpr int A_H    = (MODE==1) ? 2048 : 8192;   // halves per stage
    constexpr int B_H    = 128*72;                    // 9216 halves per stage
    constexpr int STAGES = (MODE==2) ? 2 : 3;
    extern __shared__ __half smh[];
    __half* as  = smh;
    __half* bsm = smh + STAGES*A_H;
    float*  cwT = (float*)(smh + STAGES*(A_H + B_H));  // MODE2 only
    int*    ciT = (int*)(cwT + 4608);

    const int t = threadIdx.x;
    const int wid = t >> 5, lane = t & 31, g = lane >> 2, tig = lane & 3;
    const int px0 = blockIdx.x << 7;
    const int bI = px0 >> 14, y = (px0 >> 7) & 127;
    const int yblk = (MODE==0) ? blockIdx.y : 0;
    const int co0 = yblk << 7;
    const int halfsel = (MODE==1) ? 0 : (wid >> 2);
    const int cow = halfsel * 64;
    const int pxw = (MODE==1) ? (wid << 4) : ((wid & 3) << 5);

    float acc[MT][NT][4];
    #pragma unroll
    for (int mt = 0; mt < MT; mt++)
        #pragma unroll
        for (int nt = 0; nt < NT; nt++)
            #pragma unroll
            for (int j = 0; j < 4; j++) acc[mt][nt][j] = 0.f;

    // ---- MODE 2: precompute bilinear corner tables ----
    if (MODE == 2) {
        const float* ob = g_off + (((size_t)bI*27) << 14) + y*WW;
        for (int pt = t; pt < 1152; pt += 256) {
            int tap = pt >> 7, px = pt & 127;
            float dy = ob[((size_t)(2*tap  ) << 14) + px];
            float dx = ob[((size_t)(2*tap+1) << 14) + px];
            float mk = ob[((size_t)(18+tap ) << 14) + px];
            float yy = dy + (float)(y  + tap/3 - 1);
            float xx = dx + (float)(px + tap%3 - 1);
            float y0f = floorf(yy), x0f = floorf(xx);
            float wy = yy - y0f, wx = xx - x0f;
            int y0 = (int)y0f, x0 = (int)x0f;
            float fw[4]; int fi[4];
            #pragma unroll
            for (int cnr = 0; cnr < 4; cnr++) {
                int ddy = cnr >> 1, ddx = cnr & 1;
                int yi = y0 + ddy, xi = x0 + ddx;
                bool valid = ((unsigned)yi < (unsigned)HH) && ((unsigned)xi < (unsigned)WW);
                int yc = min(max(yi, 0), HH-1);
                int xc = min(max(xi, 0), WW-1);
                float wgt = (ddy ? wy : 1.f - wy) * (ddx ? wx : 1.f - wx) * mk;
                fw[cnr] = valid ? wgt : 0.f;
                fi[cnr] = yc*WW + xc;
            }
            ((float4*)cwT)[pt] = make_float4(fw[0], fw[1], fw[2], fw[3]);
            ((int4*)ciT)[pt]   = make_int4(fi[0], fi[1], fi[2], fi[3]);
        }
        __syncthreads();
    }

    // ---- staging helper (caller commits); c = 64-k chunk index ----
    auto stage = [&](int c, int buf) {
        if (MODE == 0) {
            #pragma unroll
            for (int j = 0; j < 4; j++) {
                int idx = t + j*256;                 // 1024 cp16s
                int sub = idx >> 9, oks = (idx >> 8) & 1, off = idx & 255;
                unsigned d = (unsigned)__cvta_generic_to_shared(as + buf*A_H + idx*8);
                cp16(d, g_wAh + (size_t)(2*c+sub)*8192 + oks*4096 + yblk*2048 + off*8, 16);
            }
        } else if (MODE == 2) {
            #pragma unroll
            for (int j = 0; j < 4; j++) {
                int idx = t + j*256;
                int sub = idx >> 9, rest = idx & 511;
                unsigned d = (unsigned)__cvta_generic_to_shared(as + buf*A_H + idx*8);
                cp16(d, g_wth + (size_t)(2*c+sub)*4096 + rest*8, 16);
            }
        } else {
            int sub = t >> 7, rest = t & 127;
            unsigned d = (unsigned)__cvta_generic_to_shared(as + buf*A_H + t*8);
            cp16(d, g_wMh + (size_t)(2*c+sub)*1024 + rest*8, 16);
        }
        if (MODE != 2) {
            const __half* srcT = (MODE==0) ? g_xTh : g_xattTh;
            int tap = c >> 1, ci0 = (c & 1) << 6;
            int dy = tap/3 - 1, dxx = tap - (tap/3)*3 - 1;
            int row = t >> 1;
            int yp = y + dy, xp = row + dxx;
            bool valid = ((unsigned)yp < 128u) && ((unsigned)xp < 128u);
            int sz = valid ? 16 : 0;
            const __half* src = srcT + ((size_t)((bI<<14) + (valid ? (yp<<7)+xp : 0)))*CHN + ci0;
            #pragma unroll
            for (int j = 0; j < 4; j++) {
                int seg = (t & 1)*4 + j;             // 0..7, 16B each
                unsigned d = (unsigned)__cvta_generic_to_shared(
                    bsm + buf*B_H + row*72 + seg*8);
                cp16(d, src + seg*8, sz);
            }
        }
    };

    // ==================== MODE 0 / 1: 3-stage pipeline ====================
    if (MODE != 2) {
        stage(0, 0); cp_commit();
        stage(1, 1); cp_commit();
        for (int c = 0; c < NC; c++) {
            if (c < NC-1) cp_wait1(); else cp_wait0();
            __syncthreads();
            if (c + 2 < NC) { stage(c+2, (c+2)%3); cp_commit(); }
            const uint4*  ab = (const uint4*)(as + (c%3)*A_H);
            const __half* bb = bsm + (c%3)*B_H;
            #pragma unroll
            for (int s = 0; s < 4; s++) {
                uint4 af[MT];
                #pragma unroll
                for (int mt = 0; mt < MT; mt++)
                    af[mt] = ab[(s*NH + halfsel)*MT*32 + mt*32 + lane];
                #pragma unroll
                for (int nt = 0; nt < NT; nt++) {
                    const __half* bp = bb + (pxw + nt*8 + g)*72 + s*16 + tig*2;
                    uint32_t b0 = *(const uint32_t*)bp;
                    uint32_t b1 = *(const uint32_t*)(bp + 8);
                    #pragma unroll
                    for (int mt = 0; mt < MT; mt++)
                        mma_f16(acc[mt][nt], (const uint32_t*)&af[mt], b0, b1);
                }
            }
        }
    }
    // ============ MODE 2: 2-stage + register-pipelined gather =============
    else {
        stage(0, 0); cp_commit();
        {   // gather chunk 0 (tap 0, ci 0..63)
            const float4* fw0 = (const float4*)cwT;
            const int4*   iw0 = (const int4*)ciT;
            #pragma unroll
            for (int h = 0; h < 2; h++) {
                const __half* xb = g_xattTh + ((size_t)(bI << 14))*CHN + h*32 + lane;
                __half* bd = bsm + h*32 + lane;
                #pragma unroll 4
                for (int idx = 0; idx < 16; idx++) {
                    int px = wid + idx*8;
                    float4 f = fw0[px]; int4 ix = iw0[px];
                    float v = f.x*__half2float(xb[(size_t)ix.x*CHN])
                            + f.y*__half2float(xb[(size_t)ix.y*CHN])
                            + f.z*__half2float(xb[(size_t)ix.z*CHN])
                            + f.w*__half2float(xb[(size_t)ix.w*CHN]);
                    bd[px*72] = __float2half(v);
                }
            }
        }
        cp_wait0(); __syncthreads();

        for (int c = 0; c < NC; c++) {
            const int buf = c & 1;
            if (c < NC-1) { stage(c+1, buf^1); cp_commit(); }

            const __half* xbb = nullptr; const float4* fw = nullptr;
            const int4* iwp = nullptr; __half* bdb = nullptr;
            if (c < NC-1) {
                int cn = c + 1, tapn = cn >> 1, cib = (cn & 1) << 6;
                xbb = g_xattTh + ((size_t)(bI << 14))*CHN + cib + lane;
                fw  = ((const float4*)cwT) + tapn*128;
                iwp = ((const int4*)ciT)  + tapn*128;
                bdb = bsm + (buf^1)*B_H + lane;
            }

            const uint4*  ab = (const uint4*)(as + buf*A_H);
            const __half* bb = bsm + buf*B_H;
            #pragma unroll
            for (int s = 0; s < 4; s++) {
                uint4 af[MT];
                #pragma unroll
                for (int mt = 0; mt < MT; mt++)
                    af[mt] = ab[(s*2 + halfsel)*128 + mt*32 + lane];
                #pragma unroll
                for (int sub = 0; sub < 2; sub++) {
                    const int sl = s*2 + sub;            // 0..7
                    const int hh = sl >> 2, qb = sl & 3;
                    float lv[16]; int pxa[4];
                    if (c < NC-1) {
                        const __half* xb = xbb + hh*32;
                        #pragma unroll
                        for (int q = 0; q < 4; q++) {
                            int px = wid + (qb*4 + q)*8;
                            pxa[q] = px;
                            int4 ix = iwp[px];
                            lv[q*4+0] = __half2float(xb[(size_t)ix.x*CHN]);
                            lv[q*4+1] = __half2float(xb[(size_t)ix.y*CHN]);
                            lv[q*4+2] = __half2float(xb[(size_t)ix.z*CHN]);
                            lv[q*4+3] = __half2float(xb[(size_t)ix.w*CHN]);
                        }
                    }
                    #pragma unroll
                    for (int nt = sub*2; nt < sub*2 + 2; nt++) {
                        const __half* bp = bb + (pxw + nt*8 + g)*72 + s*16 + tig*2;
                        uint32_t b0 = *(const uint32_t*)bp;
                        uint32_t b1 = *(const uint32_t*)(bp + 8);
                        #pragma unroll
                        for (int mt = 0; mt < MT; mt++)
                            mma_f16(acc[mt][nt], (const uint32_t*)&af[mt], b0, b1);
                    }
                    if (c < NC-1) {
                        const __half* xb2 = xbb + hh*32;
                        __half* bd = bdb + hh*32;
                        (void)xb2;
                        #pragma unroll
                        for (int q = 0; q < 4; q++) {
                            float4 f = fw[pxa[q]];
                            float v = f.x*lv[q*4]   + f.y*lv[q*4+1]
                                    + f.z*lv[q*4+2] + f.w*lv[q*4+3];
                            bd[pxa[q]*72] = __float2half(v);
                        }
                    }
                }
            }
            if (c < NC-1) { cp_wait0(); __syncthreads(); }
        }
    }

    // ---- epilogue ----
    const int prem = px0 & (HW-1);
    #pragma unroll
    for (int mt = 0; mt < MT; mt++) {
        #pragma unroll
        for (int r = 0; r < 2; r++) {
            const int coL = cow + mt*16 + r*8 + g;
            const int coG = co0 + coL;
            float bv = 0.f;
            float* planeF = nullptr; __half* planeH = nullptr;
            bool sig = false, dostats = false; int sidx = 0;
            if (MODE == 0) {
                bv = g_biasA[coG];
                if (coG < 128) { planeH = g_attnH + ((size_t)(bI*CHN + coG) << 14); sig = true; }
                else {
                    planeH = g_featH + ((size_t)(bI*CHN + coG - 128) << 14);
                    dostats = true; sidx = (bI*CHN + coG - 128)*2;
                }
            } else if (MODE == 2) {
                bv = g_biasO[coL];
                planeF = g_dconv + ((size_t)(bI*CHN + coL) << 14);
                dostats = true; sidx = (BB*CHN + bI*CHN + coL)*2;
            } else {
                bv = g_biasM[coL];
                if (coL < 27) { planeF = g_off + ((size_t)(bI*27 + coL) << 14); sig = (coL >= 18); }
            }
            float s = 0.f, q = 0.f;
            #pragma unroll
            for (int nt = 0; nt < NT; nt++) {
                float v0 = acc[mt][nt][r*2]   + bv;
                float v1 = acc[mt][nt][r*2+1] + bv;
                if (sig) { v0 = sigmoidf(v0); v1 = sigmoidf(v1); }
                int col = pxw + nt*8 + 2*tig;
                if (planeF) *(float2*)&planeF[prem + col] = make_float2(v0, v1);
                if (planeH) *(__half2*)&planeH[prem + col] = __floats2half2_rn(v0, v1);
                s += v0 + v1; q += v0*v0 + v1*v1;
            }
            if (dostats) {
                s += __shfl_xor_sync(0xffffffffu, s, 1);
                s += __shfl_xor_sync(0xffffffffu, s, 2);
                q += __shfl_xor_sync(0xffffffffu, q, 1);
                q += __shfl_xor_sync(0xffffffffu, q, 2);
                if (tig == 0) {
                    atomicAdd(&g_stats[sidx],   s);
                    atomicAdd(&g_stats[sidx+1], q);
                }
            }
        }
    }
}

// ---- x_attned = lrelu(IN(feat)) * attn ; writes NHWC fp16 only ----
__global__ __launch_bounds__(256) void xatt_k() {
    __shared__ float s[32][133];
    int bid = blockIdx.x;
    int pg = bid & 127, cg = (bid >> 7) & 3, b = bid >> 9;
    int t = threadIdx.x;
    int px0 = pg << 7;
    #pragma unroll
    for (int j = 0; j < 16; j++) {
        int idx = t + j*256;
        int ch = idx >> 7, px = idx & 127;
        int plane = b*CHN + (cg<<5) + ch;
        size_t gi = ((size_t)plane << 14) + px0 + px;
        float su = g_stats[2*plane], sq = g_stats[2*plane+1];
        float mu = su * (1.0f/HW);
        float rs = rsqrtf(sq * (1.0f/HW) - mu*mu + 1e-5f);
        float v = (__half2float(g_featH[gi]) - mu)*rs;
        v = v > 0.f ? v : 0.2f*v;
        s[ch][px] = v * __half2float(g_attnH[gi]);
    }
    __syncthreads();
    #pragma unroll
    for (int j = 0; j < 16; j++) {
        int idx = t + j*256;
        int px = idx >> 5, ch = idx & 31;
        g_xattTh[((size_t)((b<<14) + px0 + px))*CHN + (cg<<5) + ch] =
            __float2half(s[ch][px]);
    }
}

// ---- final: out = xatt + lrelu(IN(dconv)) * (1 - attn)  (smem-tiled) ----
__global__ __launch_bounds__(256) void final_k(float* __restrict__ out) {
    __shared__ float s[32][133];
    int bid = blockIdx.x;
    int pg = bid & 127, cg = (bid >> 7) & 3, b = bid >> 9;
    int t = threadIdx.x;
    int px0 = pg << 7;
    // phase 1: load xatt from NHWC fp16 into smem [ch][px]
    #pragma unroll
    for (int j = 0; j < 16; j++) {
        int idx = t + j*256;
        int px = idx >> 5, ch = idx & 31;
        s[ch][px] = __half2float(
            g_xattTh[((size_t)((b<<14) + px0 + px))*CHN + (cg<<5) + ch]);
    }
    __syncthreads();
    // phase 2: NCHW-contiguous compute + store
    #pragma unroll
    for (int j = 0; j < 16; j++) {
        int idx = t + j*256;
        int ch = idx >> 7, px = idx & 127;
        int plane = b*CHN + (cg<<5) + ch;
        size_t gi = ((size_t)plane << 14) + px0 + px;
        float su = g_stats[2*(BB*CHN + plane)], sq = g_stats[2*(BB*CHN + plane)+1];
        float mu = su * (1.0f/HW);
        float rs = rsqrtf(sq * (1.0f/HW) - mu*mu + 1e-5f);
        float v = (g_dconv[gi] - mu)*rs;
        v = v > 0.f ? v : 0.2f*v;
        float a = __half2float(g_attnH[gi]);
        out[gi] = s[ch][px] + v*(1.f - a);
    }
}

// ---------------- launch ----------------
extern "C" void kernel_launch(void* const* d_in, const int* in_sizes, int n_in,
                              void* d_out, int out_size) {
    const float* x      = (const float*)d_in[0];
    const float* w_attn = (const float*)d_in[1];
    const float* b_attn = (const float*)d_in[2];
    const float* w_feat = (const float*)d_in[3];
    const float* b_feat = (const float*)d_in[4];
    const float* w_org  = (const float*)d_in[5];
    const float* b_org  = (const float*)d_in[6];
    const float* w_off  = (const float*)d_in[7];
    const float* b_off  = (const float*)d_in[8];
    const float* w_mask = (const float*)d_in[9];
    const float* b_mask = (const float*)d_in[10];
    float* out = (float*)d_out;

    const int SM_M0 = 3*(8192 + 9216)*2;                     // 104448
    const int SM_M1 = 3*(2048 + 9216)*2;                     // 67584
    const int SM_M2 = 2*(8192 + 9216)*2 + 4608*4 + 4608*4;   // 106496
    cudaFuncSetAttribute(gemm_k<0>, cudaFuncAttributeMaxDynamicSharedMemorySize, SM_M0);
    cudaFuncSetAttribute(gemm_k<1>, cudaFuncAttributeMaxDynamicSharedMemorySize, SM_M1);
    cudaFuncSetAttribute(gemm_k<2>, cudaFuncAttributeMaxDynamicSharedMemorySize, SM_M2);

    prep_k<<<1152, 256>>>(w_attn, w_feat, w_org, w_off, w_mask,
                          b_attn, b_feat, b_org, b_off, b_mask);
    transpose_k<<<2048, 256>>>(x);
    gemm_k<0><<<dim3(512, 2), 256, SM_M0>>>();     // attn + feat conv
    xatt_k<<<2048, 256>>>();
    gemm_k<1><<<512, 256, SM_M1>>>();              // offset + mask conv
    gemm_k<2><<<512, 256, SM_M2>>>();              // fused gather + deform einsum
    final_k<<<2048, 256>>>(out);
}

// round 17
// speedup vs baseline: 1.1028x; 1.0511x over previous
#include <cuda_runtime.h>
#include <cuda_fp16.h>
#include <cstdint>

#define BB  4
#define CHN 128
#define HH  128
#define WW  128
#define HW  16384
#define K2C 1152
#define NPX (BB*HW)
#define NC  18                      // 64-k chunks

// ---------------- scratch (device globals; allocation-free) ----------------
__device__ __half g_xTh   [(size_t)NPX*CHN];   // x in NHWC, fp16
__device__ __half g_xattTh[(size_t)NPX*CHN];   // x_attned in NHWC, fp16
__device__ __half g_attnH [(size_t)BB*CHN*HW]; // sigmoid(conv_attn), NCHW fp16
__device__ __half g_featH [(size_t)BB*CHN*HW]; // raw conv_feat, NCHW fp16
__device__ float g_off  [(size_t)BB*27*HW];    // 18 offsets + 9 sigmoided masks
__device__ float g_dconv[(size_t)BB*CHN*HW];   // deform conv output, fp32
// fp16 fragment-packed weights (m16n8k16 layout), indexed by 32-k chunks
__device__ __half g_wAh[36*2*4*4*32*8];        // [c32][ks2][hb4][mt4][lane][8] attn+feat
__device__ __half g_wth[36*2*2*4*32*8];        // [c32][ks2][hb2][mt4][lane][8] w_org
__device__ __half g_wMh[36*2*2*32*8];          // [c32][ks2][mt2][lane][8]      off/mask
__device__ float g_biasA[256];
__device__ float g_biasM[32];
__device__ float g_biasO[128];
__device__ float g_stats[2*BB*CHN*2];

__device__ __forceinline__ float sigmoidf(float v) { return 1.0f/(1.0f + __expf(-v)); }

__device__ __forceinline__ void mma_f16(float* d, const uint32_t* a,
                                        uint32_t b0, uint32_t b1) {
    asm volatile(
        "mma.sync.aligned.m16n8k16.row.col.f32.f16.f16.f32 "
        "{%0,%1,%2,%3},{%4,%5,%6,%7},{%8,%9},{%0,%1,%2,%3};\n"
        : "+f"(d[0]), "+f"(d[1]), "+f"(d[2]), "+f"(d[3])
        : "r"(a[0]), "r"(a[1]), "r"(a[2]), "r"(a[3]), "r"(b0), "r"(b1));
}

__device__ __forceinline__ void cp16(unsigned dst, const void* src, int srcsize) {
    asm volatile("cp.async.cg.shared.global [%0], [%1], 16, %2;\n"
                 :: "r"(dst), "l"(src), "r"(srcsize));
}
__device__ __forceinline__ void cp_commit() { asm volatile("cp.async.commit_group;\n"); }
__device__ __forceinline__ void cp_wait0()  { asm volatile("cp.async.wait_group 0;\n"); }
__device__ __forceinline__ void cp_wait1()  { asm volatile("cp.async.wait_group 1;\n"); }

// ---------------- prep: pack weights into fp16 fragments ----------------
__global__ void prep_k(const float* __restrict__ w_attn, const float* __restrict__ w_feat,
                       const float* __restrict__ w_org,  const float* __restrict__ w_off,
                       const float* __restrict__ w_mask,
                       const float* __restrict__ b_attn, const float* __restrict__ b_feat,
                       const float* __restrict__ b_org,  const float* __restrict__ b_off,
                       const float* __restrict__ b_mask)
{
    int i = blockIdx.x*256 + threadIdx.x;       // 0 .. 294911
    {   // g_wAh
        int e = i & 7, lane = (i>>3) & 31, mt = (i>>8) & 3,
            hb = (i>>10) & 3, ks = (i>>12) & 1, c = i >> 13;
        int g = lane>>2, tig = lane&3, r = e>>1, h = e&1;
        int co = hb*64 + mt*16 + g + ((r&1) ? 8 : 0);
        int k  = c*32 + ks*16 + tig*2 + h + ((r&2) ? 8 : 0);
        int tap = k >> 7, ci = k & 127;
        float v = (co < 128) ? w_attn[(co*128+ci)*9 + tap]
                             : w_feat[((co-128)*128+ci)*9 + tap];
        g_wAh[i] = __float2half(v);
    }
    if (i < 36*2*2*4*32*8) {   // g_wth
        int e = i & 7, lane = (i>>3) & 31, mt = (i>>8) & 3,
            hb = (i>>10) & 1, ks = (i>>11) & 1, c = i >> 12;
        int g = lane>>2, tig = lane&3, r = e>>1, h = e&1;
        int co = hb*64 + mt*16 + g + ((r&1) ? 8 : 0);
        int k  = c*32 + ks*16 + tig*2 + h + ((r&2) ? 8 : 0);
        int tap = k >> 7, ci = k & 127;
        g_wth[i] = __float2half(w_org[(co*128+ci)*9 + tap]);
    }
    if (i < 36*2*2*32*8) {     // g_wMh
        int e = i & 7, lane = (i>>3) & 31, mt = (i>>8) & 1,
            ks = (i>>9) & 1, c = i >> 10;
        int g = lane>>2, tig = lane&3, r = e>>1, h = e&1;
        int co = mt*16 + g + ((r&1) ? 8 : 0);
        int k  = c*32 + ks*16 + tig*2 + h + ((r&2) ? 8 : 0);
        int tap = k >> 7, ci = k & 127;
        float v = 0.f;
        if (co < 18)      v = w_off [(co*128+ci)*9 + tap];
        else if (co < 27) v = w_mask[((co-18)*128+ci)*9 + tap];
        g_wMh[i] = __float2half(v);
    }
    if (i < 256) g_biasA[i] = (i < 128) ? b_attn[i] : b_feat[i-128];
    if (i < 128) g_biasO[i] = b_org[i];
    if (i < 32)  g_biasM[i] = (i < 18) ? b_off[i] : (i < 27 ? b_mask[i-18] : 0.f);
    if (i < 2*BB*CHN*2) g_stats[i] = 0.f;
}

// ---------------- NCHW -> NHWC(fp16) transpose of x ----------------
__global__ __launch_bounds__(256) void transpose_k(const float* __restrict__ x) {
    __shared__ float s[32][133];
    int bid = blockIdx.x;
    int pg = bid & 127, cg = (bid >> 7) & 3, b = bid >> 9;
    int t = threadIdx.x;
    int px0 = pg << 7;
    #pragma unroll
    for (int j = 0; j < 4; j++) {
        int idx4 = t + j*256;                // 1024 float4s (global)
        int ch = idx4 >> 5, px = (idx4 & 31) << 2;
        float4 v = *(const float4*)&x[((size_t)(b*CHN + (cg<<5) + ch) << 14) + px0 + px];
        s[ch][px]   = v.x;
        s[ch][px+1] = v.y;
        s[ch][px+2] = v.z;
        s[ch][px+3] = v.w;
    }
    __syncthreads();
    #pragma unroll
    for (int j = 0; j < 8; j++) {
        int idx2 = t + j*256;                // 2048 half2s
        int px = idx2 >> 4, chp = idx2 & 15;
        __half2 h = __floats2half2_rn(s[chp*2][px], s[chp*2+1][px]);
        *(__half2*)&g_xTh[((size_t)((b<<14) + px0 + px))*CHN + (cg<<5) + chp*2] = h;
    }
}

// ---------------- generic fp16 GEMM, 64-k chunks -------------------------
// MODE 0: attn+feat conv; MODE 1: off/mask conv; MODE 2: fused deform einsum
template<int MODE>
__global__ __launch_bounds__(256, 2) void gemm_k()
{
    constexpr int MT     = (MODE==1) ? 2 : 4;
    constexpr int NT     = (MODE==1) ? 2 : 4;
    constexpr int NH     = (MODE==1) ? 1 : 2;
    constexpr int A_H    = (MODE==1) ? 2048 : 8192;   // halves per stage
    constexpr int B_H    = 128*72;                    // 9216 halves per stage
    constexpr int STAGES = (MODE==2) ? 2 : 3;
    extern __shared__ __half smh[];
    __half* as  = smh;
    __half* bsm = smh + STAGES*A_H;
    float*  cwT = (float*)(smh + STAGES*(A_H + B_H));  // MODE2 only
    int*    ciT = (int*)(cwT + 4608);

    const int t = threadIdx.x;
    const int wid = t >> 5, lane = t & 31, g = lane >> 2, tig = lane & 3;
    const int px0 = blockIdx.x << 7;
    const int bI = px0 >> 14, y = (px0 >> 7) & 127;
    const int yblk = (MODE==0) ? blockIdx.y : 0;
    const int co0 = yblk << 7;
    const int halfsel = (MODE==1) ? 0 : (wid >> 2);
    const int cow = halfsel * 64;
    const int pxw = (MODE==1) ? (wid << 4) : ((wid & 3) << 5);

    float acc[MT][NT][4];
    #pragma unroll
    for (int mt = 0; mt < MT; mt++)
        #pragma unroll
        for (int nt = 0; nt < NT; nt++)
            #pragma unroll
            for (int j = 0; j < 4; j++) acc[mt][nt][j] = 0.f;

    // ---- MODE 2: precompute bilinear corner tables ----
    if (MODE == 2) {
        const float* ob = g_off + (((size_t)bI*27) << 14) + y*WW;
        for (int pt = t; pt < 1152; pt += 256) {
            int tap = pt >> 7, px = pt & 127;
            float dy = ob[((size_t)(2*tap  ) << 14) + px];
            float dx = ob[((size_t)(2*tap+1) << 14) + px];
            float mk = ob[((size_t)(18+tap ) << 14) + px];
            float yy = dy + (float)(y  + tap/3 - 1);
            float xx = dx + (float)(px + tap%3 - 1);
            float y0f = floorf(yy), x0f = floorf(xx);
            float wy = yy - y0f, wx = xx - x0f;
            int y0 = (int)y0f, x0 = (int)x0f;
            float fw[4]; int fi[4];
            #pragma unroll
            for (int cnr = 0; cnr < 4; cnr++) {
                int ddy = cnr >> 1, ddx = cnr & 1;
                int yi = y0 + ddy, xi = x0 + ddx;
                bool valid = ((unsigned)yi < (unsigned)HH) && ((unsigned)xi < (unsigned)WW);
                int yc = min(max(yi, 0), HH-1);
                int xc = min(max(xi, 0), WW-1);
                float wgt = (ddy ? wy : 1.f - wy) * (ddx ? wx : 1.f - wx) * mk;
                fw[cnr] = valid ? wgt : 0.f;
                fi[cnr] = yc*WW + xc;
            }
            ((float4*)cwT)[pt] = make_float4(fw[0], fw[1], fw[2], fw[3]);
            ((int4*)ciT)[pt]   = make_int4(fi[0], fi[1], fi[2], fi[3]);
        }
        __syncthreads();
    }

    // ---- staging helper (caller commits); c = 64-k chunk index ----
    auto stage = [&](int c, int buf) {
        if (MODE == 0) {
            #pragma unroll
            for (int j = 0; j < 4; j++) {
                int idx = t + j*256;                 // 1024 cp16s
                int sub = idx >> 9, oks = (idx >> 8) & 1, off = idx & 255;
                unsigned d = (unsigned)__cvta_generic_to_shared(as + buf*A_H + idx*8);
                cp16(d, g_wAh + (size_t)(2*c+sub)*8192 + oks*4096 + yblk*2048 + off*8, 16);
            }
        } else if (MODE == 2) {
            #pragma unroll
            for (int j = 0; j < 4; j++) {
                int idx = t + j*256;
                int sub = idx >> 9, rest = idx & 511;
                unsigned d = (unsigned)__cvta_generic_to_shared(as + buf*A_H + idx*8);
                cp16(d, g_wth + (size_t)(2*c+sub)*4096 + rest*8, 16);
            }
        } else {
            int sub = t >> 7, rest = t & 127;
            unsigned d = (unsigned)__cvta_generic_to_shared(as + buf*A_H + t*8);
            cp16(d, g_wMh + (size_t)(2*c+sub)*1024 + rest*8, 16);
        }
        if (MODE != 2) {
            const __half* srcT = (MODE==0) ? g_xTh : g_xattTh;
            int tap = c >> 1, ci0 = (c & 1) << 6;
            int dy = tap/3 - 1, dxx = tap - (tap/3)*3 - 1;
            int row = t >> 1;
            int yp = y + dy, xp = row + dxx;
            bool valid = ((unsigned)yp < 128u) && ((unsigned)xp < 128u);
            int sz = valid ? 16 : 0;
            const __half* src = srcT + ((size_t)((bI<<14) + (valid ? (yp<<7)+xp : 0)))*CHN + ci0;
            #pragma unroll
            for (int j = 0; j < 4; j++) {
                int seg = (t & 1)*4 + j;             // 0..7, 16B each
                unsigned d = (unsigned)__cvta_generic_to_shared(
                    bsm + buf*B_H + row*72 + seg*8);
                cp16(d, src + seg*8, sz);
            }
        }
    };

    // ==================== MODE 0 / 1: 3-stage pipeline ====================
    if (MODE != 2) {
        stage(0, 0); cp_commit();
        stage(1, 1); cp_commit();
        for (int c = 0; c < NC; c++) {
            if (c < NC-1) cp_wait1(); else cp_wait0();
            __syncthreads();
            if (c + 2 < NC) { stage(c+2, (c+2)%3); cp_commit(); }
            const uint4*  ab = (const uint4*)(as + (c%3)*A_H);
            const __half* bb = bsm + (c%3)*B_H;
            #pragma unroll
            for (int s = 0; s < 4; s++) {
                uint4 af[MT];
                #pragma unroll
                for (int mt = 0; mt < MT; mt++)
                    af[mt] = ab[(s*NH + halfsel)*MT*32 + mt*32 + lane];
                #pragma unroll
                for (int nt = 0; nt < NT; nt++) {
                    const __half* bp = bb + (pxw + nt*8 + g)*72 + s*16 + tig*2;
                    uint32_t b0 = *(const uint32_t*)bp;
                    uint32_t b1 = *(const uint32_t*)(bp + 8);
                    #pragma unroll
                    for (int mt = 0; mt < MT; mt++)
                        mma_f16(acc[mt][nt], (const uint32_t*)&af[mt], b0, b1);
                }
            }
        }
    }
    // ============ MODE 2: 2-stage + register-pipelined gather =============
    else {
        stage(0, 0); cp_commit();
        {   // gather chunk 0 (tap 0, ci 0..63)
            const float4* fw0 = (const float4*)cwT;
            const int4*   iw0 = (const int4*)ciT;
            #pragma unroll
            for (int h = 0; h < 2; h++) {
                const __half* xb = g_xattTh + ((size_t)(bI << 14))*CHN + h*32 + lane;
                __half* bd = bsm + h*32 + lane;
                #pragma unroll 4
                for (int idx = 0; idx < 16; idx++) {
                    int px = wid + idx*8;
                    float4 f = fw0[px]; int4 ix = iw0[px];
                    float v = f.x*__half2float(xb[(size_t)ix.x*CHN])
                            + f.y*__half2float(xb[(size_t)ix.y*CHN])
                            + f.z*__half2float(xb[(size_t)ix.z*CHN])
                            + f.w*__half2float(xb[(size_t)ix.w*CHN]);
                    bd[px*72] = __float2half(v);
                }
            }
        }
        cp_wait0(); __syncthreads();

        for (int c = 0; c < NC; c++) {
            const int buf = c & 1;
            if (c < NC-1) { stage(c+1, buf^1); cp_commit(); }

            const __half* xbb = nullptr; const float4* fw = nullptr;
            const int4* iwp = nullptr; __half* bdb = nullptr;
            if (c < NC-1) {
                int cn = c + 1, tapn = cn >> 1, cib = (cn & 1) << 6;
                xbb = g_xattTh + ((size_t)(bI << 14))*CHN + cib + lane;
                fw  = ((const float4*)cwT) + tapn*128;
                iwp = ((const int4*)ciT)  + tapn*128;
                bdb = bsm + (buf^1)*B_H + lane;
            }

            const uint4*  ab = (const uint4*)(as + buf*A_H);
            const __half* bb = bsm + buf*B_H;
            #pragma unroll
            for (int s = 0; s < 4; s++) {
                uint4 af[MT];
                #pragma unroll
                for (int mt = 0; mt < MT; mt++)
                    af[mt] = ab[(s*2 + halfsel)*128 + mt*32 + lane];
                #pragma unroll
                for (int sub = 0; sub < 2; sub++) {
                    const int sl = s*2 + sub;            // 0..7
                    const int hh = sl >> 2, qb = sl & 3;
                    float lv[16]; int pxa[4];
                    if (c < NC-1) {
                        const __half* xb = xbb + hh*32;
                        #pragma unroll
                        for (int q = 0; q < 4; q++) {
                            int px = wid + (qb*4 + q)*8;
                            pxa[q] = px;
                            int4 ix = iwp[px];
                            lv[q*4+0] = __half2float(xb[(size_t)ix.x*CHN]);
                            lv[q*4+1] = __half2float(xb[(size_t)ix.y*CHN]);
                            lv[q*4+2] = __half2float(xb[(size_t)ix.z*CHN]);
                            lv[q*4+3] = __half2float(xb[(size_t)ix.w*CHN]);
                        }
                    }
                    #pragma unroll
                    for (int nt = sub*2; nt < sub*2 + 2; nt++) {
                        const __half* bp = bb + (pxw + nt*8 + g)*72 + s*16 + tig*2;
                        uint32_t b0 = *(const uint32_t*)bp;
                        uint32_t b1 = *(const uint32_t*)(bp + 8);
                        #pragma unroll
                        for (int mt = 0; mt < MT; mt++)
                            mma_f16(acc[mt][nt], (const uint32_t*)&af[mt], b0, b1);
                    }
                    if (c < NC-1) {
                        __half* bd = bdb + hh*32;
                        #pragma unroll
                        for (int q = 0; q < 4; q++) {
                            float4 f = fw[pxa[q]];
                            float v = f.x*lv[q*4]   + f.y*lv[q*4+1]
                                    + f.z*lv[q*4+2] + f.w*lv[q*4+3];
                            bd[pxa[q]*72] = __float2half(v);
                        }
                    }
                }
            }
            if (c < NC-1) { cp_wait0(); __syncthreads(); }
        }
    }

    // ---- epilogue ----
    const int prem = px0 & (HW-1);
    #pragma unroll
    for (int mt = 0; mt < MT; mt++) {
        #pragma unroll
        for (int r = 0; r < 2; r++) {
            const int coL = cow + mt*16 + r*8 + g;
            const int coG = co0 + coL;
            float bv = 0.f;
            float* planeF = nullptr; __half* planeH = nullptr;
            bool sig = false, dostats = false; int sidx = 0;
            if (MODE == 0) {
                bv = g_biasA[coG];
                if (coG < 128) { planeH = g_attnH + ((size_t)(bI*CHN + coG) << 14); sig = true; }
                else {
                    planeH = g_featH + ((size_t)(bI*CHN + coG - 128) << 14);
                    dostats = true; sidx = (bI*CHN + coG - 128)*2;
                }
            } else if (MODE == 2) {
                bv = g_biasO[coL];
                planeF = g_dconv + ((size_t)(bI*CHN + coL) << 14);
                dostats = true; sidx = (BB*CHN + bI*CHN + coL)*2;
            } else {
                bv = g_biasM[coL];
                if (coL < 27) { planeF = g_off + ((size_t)(bI*27 + coL) << 14); sig = (coL >= 18); }
            }
            float s = 0.f, q = 0.f;
            #pragma unroll
            for (int nt = 0; nt < NT; nt++) {
                float v0 = acc[mt][nt][r*2]   + bv;
                float v1 = acc[mt][nt][r*2+1] + bv;
                if (sig) { v0 = sigmoidf(v0); v1 = sigmoidf(v1); }
                int col = pxw + nt*8 + 2*tig;
                if (planeF) *(float2*)&planeF[prem + col] = make_float2(v0, v1);
                if (planeH) *(__half2*)&planeH[prem + col] = __floats2half2_rn(v0, v1);
                s += v0 + v1; q += v0*v0 + v1*v1;
            }
            if (dostats) {
                s += __shfl_xor_sync(0xffffffffu, s, 1);
                s += __shfl_xor_sync(0xffffffffu, s, 2);
                q += __shfl_xor_sync(0xffffffffu, q, 1);
                q += __shfl_xor_sync(0xffffffffu, q, 2);
                if (tig == 0) {
                    atomicAdd(&g_stats[sidx],   s);
                    atomicAdd(&g_stats[sidx+1], q);
                }
            }
        }
    }
}

// ---- x_attned = lrelu(IN(feat)) * attn ; writes NHWC fp16 only ----
__global__ __launch_bounds__(256) void xatt_k() {
    __shared__ float s[32][133];
    int bid = blockIdx.x;
    int pg = bid & 127, cg = (bid >> 7) & 3, b = bid >> 9;
    int t = threadIdx.x;
    int px0 = pg << 7;
    #pragma unroll
    for (int j = 0; j < 4; j++) {
        int idx4 = t + j*256;                 // 1024 quads of px
        int ch = idx4 >> 5, px = (idx4 & 31) << 2;
        int plane = b*CHN + (cg<<5) + ch;
        size_t gi = ((size_t)plane << 14) + px0 + px;
        float su = g_stats[2*plane], sq = g_stats[2*plane+1];
        float mu = su * (1.0f/HW);
        float rs = rsqrtf(sq * (1.0f/HW) - mu*mu + 1e-5f);
        uint2 fh = *(const uint2*)&g_featH[gi];
        uint2 ah = *(const uint2*)&g_attnH[gi];
        float2 f01 = __half22float2(*(__half2*)&fh.x);
        float2 f23 = __half22float2(*(__half2*)&fh.y);
        float2 a01 = __half22float2(*(__half2*)&ah.x);
        float2 a23 = __half22float2(*(__half2*)&ah.y);
        float v;
        v = (f01.x - mu)*rs; v = v > 0.f ? v : 0.2f*v; s[ch][px]   = v*a01.x;
        v = (f01.y - mu)*rs; v = v > 0.f ? v : 0.2f*v; s[ch][px+1] = v*a01.y;
        v = (f23.x - mu)*rs; v = v > 0.f ? v : 0.2f*v; s[ch][px+2] = v*a23.x;
        v = (f23.y - mu)*rs; v = v > 0.f ? v : 0.2f*v; s[ch][px+3] = v*a23.y;
    }
    __syncthreads();
    #pragma unroll
    for (int j = 0; j < 8; j++) {
        int idx2 = t + j*256;                 // 2048 half2s
        int px = idx2 >> 4, chp = idx2 & 15;
        __half2 h = __floats2half2_rn(s[chp*2][px], s[chp*2+1][px]);
        *(__half2*)&g_xattTh[((size_t)((b<<14) + px0 + px))*CHN + (cg<<5) + chp*2] = h;
    }
}

// ---- final: out = xatt + lrelu(IN(dconv)) * (1 - attn)  (smem-tiled) ----
__global__ __launch_bounds__(256) void final_k(float* __restrict__ out) {
    __shared__ float s[32][133];
    int bid = blockIdx.x;
    int pg = bid & 127, cg = (bid >> 7) & 3, b = bid >> 9;
    int t = threadIdx.x;
    int px0 = pg << 7;
    // phase 1: load xatt from NHWC fp16 into smem [ch][px]
    #pragma unroll
    for (int j = 0; j < 8; j++) {
        int idx2 = t + j*256;                 // 2048 half2s
        int px = idx2 >> 4, chp = idx2 & 15;
        __half2 h = *(const __half2*)&g_xattTh[
            ((size_t)((b<<14) + px0 + px))*CHN + (cg<<5) + chp*2];
        float2 f = __half22float2(h);
        s[chp*2][px]   = f.x;
        s[chp*2+1][px] = f.y;
    }
    __syncthreads();
    // phase 2: NCHW-contiguous vectorized compute + store
    #pragma unroll
    for (int j = 0; j < 4; j++) {
        int idx4 = t + j*256;                 // 1024 quads
        int ch = idx4 >> 5, px = (idx4 & 31) << 2;
        int plane = b*CHN + (cg<<5) + ch;
        size_t gi = ((size_t)plane << 14) + px0 + px;
        float su = g_stats[2*(BB*CHN + plane)], sq = g_stats[2*(BB*CHN + plane)+1];
        float mu = su * (1.0f/HW);
        float rs = rsqrtf(sq * (1.0f/HW) - mu*mu + 1e-5f);
        float4 d = *(const float4*)&g_dconv[gi];
        uint2 ah = *(const uint2*)&g_attnH[gi];
        float2 a01 = __half22float2(*(__half2*)&ah.x);
        float2 a23 = __half22float2(*(__half2*)&ah.y);
        float4 o; float v;
        v = (d.x - mu)*rs; v = v > 0.f ? v : 0.2f*v; o.x = s[ch][px]   + v*(1.f - a01.x);
        v = (d.y - mu)*rs; v = v > 0.f ? v : 0.2f*v; o.y = s[ch][px+1] + v*(1.f - a01.y);
        v = (d.z - mu)*rs; v = v > 0.f ? v : 0.2f*v; o.z = s[ch][px+2] + v*(1.f - a23.x);
        v = (d.w - mu)*rs; v = v > 0.f ? v : 0.2f*v; o.w = s[ch][px+3] + v*(1.f - a23.y);
        *(float4*)&out[gi] = o;
    }
}

// ---------------- launch ----------------
extern "C" void kernel_launch(void* const* d_in, const int* in_sizes, int n_in,
                              void* d_out, int out_size) {
    const float* x      = (const float*)d_in[0];
    const float* w_attn = (const float*)d_in[1];
    const float* b_attn = (const float*)d_in[2];
    const float* w_feat = (const float*)d_in[3];
    const float* b_feat = (const float*)d_in[4];
    const float* w_org  = (const float*)d_in[5];
    const float* b_org  = (const float*)d_in[6];
    const float* w_off  = (const float*)d_in[7];
    const float* b_off  = (const float*)d_in[8];
    const float* w_mask = (const float*)d_in[9];
    const float* b_mask = (const float*)d_in[10];
    float* out = (float*)d_out;

    const int SM_M0 = 3*(8192 + 9216)*2;                     // 104448
    const int SM_M1 = 3*(2048 + 9216)*2;                     // 67584
    const int SM_M2 = 2*(8192 + 9216)*2 + 4608*4 + 4608*4;   // 106496
    cudaFuncSetAttribute(gemm_k<0>, cudaFuncAttributeMaxDynamicSharedMemorySize, SM_M0);
    cudaFuncSetAttribute(gemm_k<1>, cudaFuncAttributeMaxDynamicSharedMemorySize, SM_M1);
    cudaFuncSetAttribute(gemm_k<2>, cudaFuncAttributeMaxDynamicSharedMemorySize, SM_M2);

    prep_k<<<1152, 256>>>(w_attn, w_feat, w_org, w_off, w_mask,
                          b_attn, b_feat, b_org, b_off, b_mask);
    transpose_k<<<2048, 256>>>(x);
    gemm_k<0><<<dim3(512, 2), 256, SM_M0>>>();     // attn + feat conv
    xatt_k<<<2048, 256>>>();
    gemm_k<1><<<512, 256, SM_M1>>>();              // offset + mask conv
    gemm_k<2><<<512, 256, SM_M2>>>();              // fused gather + deform einsum
    final_k<<<2048, 256>>>(out);
}